// round 1
// baseline (speedup 1.0000x reference)
#include <cuda_runtime.h>
#include <math.h>

#define BB 4
#define NSEQ 2048
#define DM 256
#define NH 4
#define DH 64
#define MW (NSEQ / 32)   // 64 mask words per row
#define ROWS (BB * NSEQ) // 8192

// ---------------- scratch (static device globals; no allocation) ----------------
__device__ float    g_xn [ROWS * DM];
__device__ float    g_sim[(size_t)BB * NSEQ * NSEQ];   // 64 MB
__device__ unsigned g_adj[ROWS * MW];                  // 2 MB bitmask
__device__ float    g_q  [ROWS * DM];
__device__ float    g_k  [ROWS * DM];
__device__ float    g_v  [ROWS * DM];
__device__ float    g_att[ROWS * DM];
__device__ float    g_o  [ROWS * DM];

// ---------------- 1) row L2-normalize ----------------
__global__ __launch_bounds__(256) void normalize_kernel(const float* __restrict__ x,
                                                        float* __restrict__ xn) {
    int row  = blockIdx.x * 8 + (threadIdx.x >> 5);
    int lane = threadIdx.x & 31;
    const float4* xr = (const float4*)(x + (size_t)row * DM);
    float4 a = xr[lane];
    float4 b = xr[lane + 32];
    float s = a.x*a.x + a.y*a.y + a.z*a.z + a.w*a.w
            + b.x*b.x + b.y*b.y + b.z*b.z + b.w*b.w;
#pragma unroll
    for (int off = 16; off; off >>= 1) s += __shfl_xor_sync(0xffffffffu, s, off);
    float inv = 1.0f / fmaxf(sqrtf(s), 1e-12f);
    float4* o = (float4*)(xn + (size_t)row * DM);
    o[lane]      = make_float4(a.x*inv, a.y*inv, a.z*inv, a.w*inv);
    o[lane + 32] = make_float4(b.x*inv, b.y*inv, b.z*inv, b.w*inv);
}

// ---------------- generic fp32 GEMM: C = A(Mx256) * B, 128x128 tile, 8x8 microtile ----------------
// TRANSB=1: C[m][n] = sum_k A[m][k]*B[n][k]   (B row-major, ldb=256)
// TRANSB=0: C[m][n] = sum_k A[m][k]*B[k][n]   (B row-major, ldb=Nn)
template <int TRANSB>
__global__ __launch_bounds__(256) void gemm_kernel(const float* __restrict__ A,
                                                   const float* __restrict__ Bm,
                                                   float* __restrict__ C,
                                                   int Nn, long sA, long sB, long sC) {
    A  += (size_t)blockIdx.z * sA;
    Bm += (size_t)blockIdx.z * sB;
    C  += (size_t)blockIdx.z * sC;
    __shared__ float As[16][132];
    __shared__ float Bs[16][132];
    int tid = threadIdx.x;
    int m0 = blockIdx.y * 128, n0 = blockIdx.x * 128;
    int tx = tid & 15, ty = tid >> 4;
    float acc[8][8];
#pragma unroll
    for (int i = 0; i < 8; i++)
#pragma unroll
        for (int j = 0; j < 8; j++) acc[i][j] = 0.0f;

    for (int k0 = 0; k0 < DM; k0 += 16) {
#pragma unroll
        for (int t = 0; t < 2; t++) {
            int idx = tid + t * 256;          // 0..511 float4 slots
            int row = idx >> 2, qq = idx & 3;
            float4 v4 = *(const float4*)(A + (size_t)(m0 + row) * DM + k0 + qq * 4);
            As[qq*4+0][row] = v4.x; As[qq*4+1][row] = v4.y;
            As[qq*4+2][row] = v4.z; As[qq*4+3][row] = v4.w;
        }
        if (TRANSB) {
#pragma unroll
            for (int t = 0; t < 2; t++) {
                int idx = tid + t * 256;
                int row = idx >> 2, qq = idx & 3;
                float4 v4 = *(const float4*)(Bm + (size_t)(n0 + row) * DM + k0 + qq * 4);
                Bs[qq*4+0][row] = v4.x; Bs[qq*4+1][row] = v4.y;
                Bs[qq*4+2][row] = v4.z; Bs[qq*4+3][row] = v4.w;
            }
        } else {
#pragma unroll
            for (int t = 0; t < 2; t++) {
                int idx = tid + t * 256;
                int kk = idx >> 5, nq = idx & 31;
                *(float4*)&Bs[kk][nq * 4] =
                    *(const float4*)(Bm + (size_t)(k0 + kk) * Nn + n0 + nq * 4);
            }
        }
        __syncthreads();
#pragma unroll
        for (int kk = 0; kk < 16; kk++) {
            float a[8], bv[8];
            *(float4*)(a)     = *(const float4*)&As[kk][ty * 8];
            *(float4*)(a + 4) = *(const float4*)&As[kk][ty * 8 + 4];
            *(float4*)(bv)     = *(const float4*)&Bs[kk][tx * 8];
            *(float4*)(bv + 4) = *(const float4*)&Bs[kk][tx * 8 + 4];
#pragma unroll
            for (int i = 0; i < 8; i++)
#pragma unroll
                for (int j = 0; j < 8; j++) acc[i][j] = fmaf(a[i], bv[j], acc[i][j]);
        }
        __syncthreads();
    }
#pragma unroll
    for (int i = 0; i < 8; i++) {
        float* cr = C + (size_t)(m0 + ty * 8 + i) * Nn + n0 + tx * 8;
        *(float4*)cr       = make_float4(acc[i][0], acc[i][1], acc[i][2], acc[i][3]);
        *(float4*)(cr + 4) = make_float4(acc[i][4], acc[i][5], acc[i][6], acc[i][7]);
    }
}

// ---------------- 3) adjacency ----------------
__global__ void zero_adj_kernel() {
    g_adj[blockIdx.x * blockDim.x + threadIdx.x] = 0u;
}

// one block per (b,n) row: iterative top-(k+1) argmax, ties -> smaller index (matches lax.top_k)
__global__ __launch_bounds__(256) void topk_kernel(const float* __restrict__ sim,
                                                   const int* __restrict__ kptr) {
    int rowid = blockIdx.x;          // b*NSEQ + n
    int n = rowid & (NSEQ - 1);
    const float* row = sim + (size_t)rowid * NSEQ;
    int tid = threadIdx.x;
    float vals[8];
#pragma unroll
    for (int i = 0; i < 8; i++) vals[i] = row[tid + 256 * i];
    int kp1 = *kptr + 1;
    __shared__ float sv[256];
    __shared__ int   si[256];
    for (int it = 0; it < kp1; it++) {
        float bv = -3.0e38f; int bi = 0x7fffffff;
#pragma unroll
        for (int i = 0; i < 8; i++) {      // strict > keeps smallest column on ties
            if (vals[i] > bv) { bv = vals[i]; bi = tid + 256 * i; }
        }
        sv[tid] = bv; si[tid] = bi;
        __syncthreads();
        for (int s = 128; s > 0; s >>= 1) {
            if (tid < s) {
                float v2 = sv[tid + s]; int i2 = si[tid + s];
                if (v2 > sv[tid] || (v2 == sv[tid] && i2 < si[tid])) { sv[tid] = v2; si[tid] = i2; }
            }
            __syncthreads();
        }
        int widx = si[0];
        if (tid == 0) {
            atomicOr(&g_adj[(size_t)rowid * MW + (widx >> 5)], 1u << (widx & 31));
            // symmetric edge: row (b, widx) gets bit n
            atomicOr(&g_adj[(size_t)(rowid - n + widx) * MW + (n >> 5)], 1u << (n & 31));
        }
        if ((widx & 255) == tid) vals[widx >> 8] = -3.0e38f;
        __syncthreads();
    }
}

// ---------------- 5) sparse masked attention: one warp per (row, head) ----------------
__global__ __launch_bounds__(128) void attn_kernel(const float* __restrict__ q,
                                                   const float* __restrict__ k,
                                                   const float* __restrict__ v,
                                                   float* __restrict__ out) {
    int rowid = blockIdx.x;          // b*NSEQ + n
    int h    = threadIdx.x >> 5;
    int lane = threadIdx.x & 31;
    __shared__ unsigned mask[MW];
    if (threadIdx.x < MW) mask[threadIdx.x] = g_adj[(size_t)rowid * MW + threadIdx.x];
    __syncthreads();

    size_t qbase = (size_t)rowid * DM + h * DH;
    float2 qv = *(const float2*)(q + qbase + 2 * lane);
    int b = rowid >> 11;             // / NSEQ
    size_t kvbase = (size_t)b * NSEQ * DM + h * DH + 2 * lane;

    float mmax = -3.0e38f, den = 0.0f, a0 = 0.0f, a1 = 0.0f;
    for (int w = 0; w < MW; w++) {
        unsigned mwd = mask[w];
        while (mwd) {
            int bit = __ffs(mwd) - 1;
            mwd &= mwd - 1;
            int m = w * 32 + bit;
            size_t off = kvbase + (size_t)m * DM;
            float2 kv = *(const float2*)(k + off);
            float s = qv.x * kv.x + qv.y * kv.y;
#pragma unroll
            for (int o2 = 16; o2; o2 >>= 1) s += __shfl_xor_sync(0xffffffffu, s, o2);
            s *= 0.125f;  // 1/sqrt(64)
            float2 vv = *(const float2*)(v + off);
            if (s > mmax) {
                float c = __expf(mmax - s);
                den *= c; a0 *= c; a1 *= c; mmax = s;
            }
            float e = __expf(s - mmax);
            den += e; a0 += e * vv.x; a1 += e * vv.y;
        }
    }
    float inv = 1.0f / den;
    *(float2*)(out + qbase + 2 * lane) = make_float2(a0 * inv, a1 * inv);
}

// ---------------- 6) residual + bias + LayerNorm (one warp per row) ----------------
__global__ __launch_bounds__(256) void ln_kernel(const float* __restrict__ x,
                                                 const float* __restrict__ o,
                                                 const float* __restrict__ bo,
                                                 const float* __restrict__ gamma,
                                                 const float* __restrict__ beta,
                                                 float* __restrict__ out) {
    int row  = blockIdx.x * 8 + (threadIdx.x >> 5);
    int lane = threadIdx.x & 31;
    size_t base = (size_t)row * DM;
    const float4* x4 = (const float4*)(x + base);
    const float4* o4 = (const float4*)(o + base);
    const float4* b4 = (const float4*)bo;
    float4 xa = x4[lane], xb = x4[lane + 32];
    float4 oa = o4[lane], ob = o4[lane + 32];
    float4 ba = b4[lane], bb = b4[lane + 32];
    float t[8];
    t[0] = xa.x + oa.x + ba.x; t[1] = xa.y + oa.y + ba.y;
    t[2] = xa.z + oa.z + ba.z; t[3] = xa.w + oa.w + ba.w;
    t[4] = xb.x + ob.x + bb.x; t[5] = xb.y + ob.y + bb.y;
    t[6] = xb.z + ob.z + bb.z; t[7] = xb.w + ob.w + bb.w;
    float sum = 0.0f;
#pragma unroll
    for (int i = 0; i < 8; i++) sum += t[i];
#pragma unroll
    for (int off = 16; off; off >>= 1) sum += __shfl_xor_sync(0xffffffffu, sum, off);
    float mu = sum * (1.0f / 256.0f);
    float vs = 0.0f;
#pragma unroll
    for (int i = 0; i < 8; i++) { float d = t[i] - mu; vs += d * d; }
#pragma unroll
    for (int off = 16; off; off >>= 1) vs += __shfl_xor_sync(0xffffffffu, vs, off);
    float r = rsqrtf(vs * (1.0f / 256.0f) + 1e-5f);
    const float4* g4 = (const float4*)gamma;
    const float4* be4 = (const float4*)beta;
    float4 ga = g4[lane], gb = g4[lane + 32];
    float4 ea = be4[lane], eb = be4[lane + 32];
    float4 y0 = make_float4((t[0]-mu)*r*ga.x + ea.x, (t[1]-mu)*r*ga.y + ea.y,
                            (t[2]-mu)*r*ga.z + ea.z, (t[3]-mu)*r*ga.w + ea.w);
    float4 y1 = make_float4((t[4]-mu)*r*gb.x + eb.x, (t[5]-mu)*r*gb.y + eb.y,
                            (t[6]-mu)*r*gb.z + eb.z, (t[7]-mu)*r*gb.w + eb.w);
    float4* op = (float4*)(out + base);
    op[lane] = y0;
    op[lane + 32] = y1;
}

// ---------------- host launcher ----------------
extern "C" void kernel_launch(void* const* d_in, const int* in_sizes, int n_in,
                              void* d_out, int out_size) {
    const float* x     = (const float*)d_in[0];
    const float* Wq    = (const float*)d_in[1];
    const float* Wk    = (const float*)d_in[2];
    const float* Wv    = (const float*)d_in[3];
    const float* Wo    = (const float*)d_in[4];
    const float* bo    = (const float*)d_in[5];
    const float* gamma = (const float*)d_in[6];
    const float* beta  = (const float*)d_in[7];
    const int*   kn    = (const int*)d_in[8];
    float* out = (float*)d_out;

    float *xn, *sim, *q, *k, *v, *att, *o;
    cudaGetSymbolAddress((void**)&xn,  g_xn);
    cudaGetSymbolAddress((void**)&sim, g_sim);
    cudaGetSymbolAddress((void**)&q,   g_q);
    cudaGetSymbolAddress((void**)&k,   g_k);
    cudaGetSymbolAddress((void**)&v,   g_v);
    cudaGetSymbolAddress((void**)&att, g_att);
    cudaGetSymbolAddress((void**)&o,   g_o);

    // 1) normalize rows
    normalize_kernel<<<ROWS / 8, 256>>>(x, xn);

    // 2) batched similarity: sim[b] = xn[b] * xn[b]^T
    dim3 gsim(NSEQ / 128, NSEQ / 128, BB);
    gemm_kernel<1><<<gsim, 256>>>(xn, xn, sim, NSEQ,
                                  (long)NSEQ * DM, (long)NSEQ * DM, (long)NSEQ * NSEQ);

    // 3) adjacency bitmask
    zero_adj_kernel<<<(ROWS * MW) / 256, 256>>>();
    topk_kernel<<<ROWS, 256>>>(sim, kn);

    // 4) QKV projections (head-contiguous layout per row)
    dim3 gp(DM / 128, ROWS / 128, 1);
    gemm_kernel<0><<<gp, 256>>>(x, Wq, q, DM, 0, 0, 0);
    gemm_kernel<0><<<gp, 256>>>(x, Wk, k, DM, 0, 0, 0);
    gemm_kernel<0><<<gp, 256>>>(x, Wv, v, DM, 0, 0, 0);

    // 5) sparse masked attention
    attn_kernel<<<ROWS, 128>>>(q, k, v, att);

    // 6) output projection + residual + bias + LayerNorm
    gemm_kernel<0><<<gp, 256>>>(att, Wo, o, DM, 0, 0, 0);
    ln_kernel<<<ROWS / 8, 256>>>(x, o, bo, gamma, beta, out);
}

// round 2
// speedup vs baseline: 1.1549x; 1.1549x over previous
#include <cuda_runtime.h>
#include <math.h>

#define BB 4
#define NSEQ 2048
#define DM 256
#define NH 4
#define DH 64
#define MW (NSEQ / 32)   // 64 mask words per row
#define ROWS (BB * NSEQ) // 8192
#define MAXK 12

// ---------------- scratch (static device globals; no allocation) ----------------
__device__ float    g_xn [ROWS * DM];
__device__ float    g_sim[(size_t)BB * NSEQ * NSEQ];   // 64 MB
__device__ unsigned g_adj[ROWS * MW];                  // 2 MB bitmask
__device__ float    g_q  [ROWS * DM];
__device__ float    g_k  [ROWS * DM];
__device__ float    g_v  [ROWS * DM];
__device__ float    g_att[ROWS * DM];
__device__ float    g_o  [ROWS * DM];

// ---------------- 1) row L2-normalize ----------------
__global__ __launch_bounds__(256) void normalize_kernel(const float* __restrict__ x,
                                                        float* __restrict__ xn) {
    int row  = blockIdx.x * 8 + (threadIdx.x >> 5);
    int lane = threadIdx.x & 31;
    const float4* xr = (const float4*)(x + (size_t)row * DM);
    float4 a = xr[lane];
    float4 b = xr[lane + 32];
    float s = a.x*a.x + a.y*a.y + a.z*a.z + a.w*a.w
            + b.x*b.x + b.y*b.y + b.z*b.z + b.w*b.w;
#pragma unroll
    for (int off = 16; off; off >>= 1) s += __shfl_xor_sync(0xffffffffu, s, off);
    float inv = 1.0f / fmaxf(sqrtf(s), 1e-12f);
    float4* o = (float4*)(xn + (size_t)row * DM);
    o[lane]      = make_float4(a.x*inv, a.y*inv, a.z*inv, a.w*inv);
    o[lane + 32] = make_float4(b.x*inv, b.y*inv, b.z*inv, b.w*inv);
}

// ---------------- generic fp32 GEMM body: 128x128 tile, 8x8 microtile, 256 thr ----------------
// TRANSB=1: C[m][n] = sum_k A[m][k]*B[n][k]   (B row-major, ldb=256)
// TRANSB=0: C[m][n] = sum_k A[m][k]*B[k][n]   (B row-major, ldb=Nn)
// Accumulators returned via acc; caller does the stores.
template <int TRANSB>
__device__ __forceinline__ void gemm_body(const float* __restrict__ A,
                                          const float* __restrict__ Bm,
                                          int m0, int n0, int Nn,
                                          float acc[8][8],
                                          float As[16][132], float Bs[16][132]) {
    int tid = threadIdx.x;
    int tx = tid & 15, ty = tid >> 4;
#pragma unroll
    for (int i = 0; i < 8; i++)
#pragma unroll
        for (int j = 0; j < 8; j++) acc[i][j] = 0.0f;

    for (int k0 = 0; k0 < DM; k0 += 16) {
#pragma unroll
        for (int t = 0; t < 2; t++) {
            int idx = tid + t * 256;          // 0..511 float4 slots
            int row = idx >> 2, qq = idx & 3;
            float4 v4 = *(const float4*)(A + (size_t)(m0 + row) * DM + k0 + qq * 4);
            As[qq*4+0][row] = v4.x; As[qq*4+1][row] = v4.y;
            As[qq*4+2][row] = v4.z; As[qq*4+3][row] = v4.w;
        }
        if (TRANSB) {
#pragma unroll
            for (int t = 0; t < 2; t++) {
                int idx = tid + t * 256;
                int row = idx >> 2, qq = idx & 3;
                float4 v4 = *(const float4*)(Bm + (size_t)(n0 + row) * DM + k0 + qq * 4);
                Bs[qq*4+0][row] = v4.x; Bs[qq*4+1][row] = v4.y;
                Bs[qq*4+2][row] = v4.z; Bs[qq*4+3][row] = v4.w;
            }
        } else {
#pragma unroll
            for (int t = 0; t < 2; t++) {
                int idx = tid + t * 256;
                int kk = idx >> 5, nq = idx & 31;
                *(float4*)&Bs[kk][nq * 4] =
                    *(const float4*)(Bm + (size_t)(k0 + kk) * Nn + n0 + nq * 4);
            }
        }
        __syncthreads();
#pragma unroll
        for (int kk = 0; kk < 16; kk++) {
            float a[8], bv[8];
            *(float4*)(a)      = *(const float4*)&As[kk][ty * 8];
            *(float4*)(a + 4)  = *(const float4*)&As[kk][ty * 8 + 4];
            *(float4*)(bv)     = *(const float4*)&Bs[kk][tx * 8];
            *(float4*)(bv + 4) = *(const float4*)&Bs[kk][tx * 8 + 4];
#pragma unroll
            for (int i = 0; i < 8; i++)
#pragma unroll
                for (int j = 0; j < 8; j++) acc[i][j] = fmaf(a[i], bv[j], acc[i][j]);
        }
        __syncthreads();
    }
}

// ---------------- 2) symmetric similarity GEMM: only upper-triangular tiles ----------------
__global__ __launch_bounds__(256) void symgemm_kernel(const float* __restrict__ xn,
                                                      float* __restrict__ C) {
    __shared__ float As[16][132];
    __shared__ float Bs[16][132];
    const float* A = xn + (size_t)blockIdx.z * NSEQ * DM;
    float* Cb = C + (size_t)blockIdx.z * NSEQ * NSEQ;

    // map linear tile id -> upper-triangular (i, j), i <= j, 16x16 tile grid
    int t = blockIdx.x, ti = 0;
    while (t >= 16 - ti) { t -= 16 - ti; ti++; }
    int tj = ti + t;
    int m0 = ti * 128, n0 = tj * 128;

    float acc[8][8];
    gemm_body<1>(A, A, m0, n0, NSEQ, acc, As, Bs);

    int tid = threadIdx.x;
    int tx = tid & 15, ty = tid >> 4;
    // normal store: C[m0+ty*8+i][n0+tx*8 ..]
#pragma unroll
    for (int i = 0; i < 8; i++) {
        float* cr = Cb + (size_t)(m0 + ty * 8 + i) * NSEQ + n0 + tx * 8;
        *(float4*)cr       = make_float4(acc[i][0], acc[i][1], acc[i][2], acc[i][3]);
        *(float4*)(cr + 4) = make_float4(acc[i][4], acc[i][5], acc[i][6], acc[i][7]);
    }
    if (ti != tj) {
        // transposed store: C[n0+tx*8+j][m0+ty*8 ..]
#pragma unroll
        for (int j = 0; j < 8; j++) {
            float* cr = Cb + (size_t)(n0 + tx * 8 + j) * NSEQ + m0 + ty * 8;
            *(float4*)cr       = make_float4(acc[0][j], acc[1][j], acc[2][j], acc[3][j]);
            *(float4*)(cr + 4) = make_float4(acc[4][j], acc[5][j], acc[6][j], acc[7][j]);
        }
    }
}

// ---------------- standard GEMM (projections) with blockIdx.z B/C select ----------------
__global__ __launch_bounds__(256) void proj_kernel(const float* __restrict__ A,
                                                   const float* __restrict__ B0,
                                                   const float* __restrict__ B1,
                                                   const float* __restrict__ B2,
                                                   float* __restrict__ C0,
                                                   float* __restrict__ C1,
                                                   float* __restrict__ C2) {
    __shared__ float As[16][132];
    __shared__ float Bs[16][132];
    int z = blockIdx.z;
    const float* Bm = (z == 0) ? B0 : ((z == 1) ? B1 : B2);
    float*       C  = (z == 0) ? C0 : ((z == 1) ? C1 : C2);
    int m0 = blockIdx.y * 128, n0 = blockIdx.x * 128;
    float acc[8][8];
    gemm_body<0>(A, Bm, m0, n0, DM, acc, As, Bs);
    int tid = threadIdx.x;
    int tx = tid & 15, ty = tid >> 4;
#pragma unroll
    for (int i = 0; i < 8; i++) {
        float* cr = C + (size_t)(m0 + ty * 8 + i) * DM + n0 + tx * 8;
        *(float4*)cr       = make_float4(acc[i][0], acc[i][1], acc[i][2], acc[i][3]);
        *(float4*)(cr + 4) = make_float4(acc[i][4], acc[i][5], acc[i][6], acc[i][7]);
    }
}

// ---------------- 3) adjacency ----------------
__global__ void zero_adj_kernel() {
    g_adj[blockIdx.x * blockDim.x + threadIdx.x] = 0u;
}

__device__ __forceinline__ bool pr_better(float v, int i, float v2, int i2) {
    return v > v2 || (v == v2 && i < i2);
}

// warp-per-row top-(k+1): per-lane sorted top-12 in registers, then 9 warp-argmax pops.
// Ties -> smaller index (matches jax.lax.top_k).
__global__ __launch_bounds__(256) void topk_kernel(const float* __restrict__ sim,
                                                   const int* __restrict__ kptr) {
    int warp  = threadIdx.x >> 5;
    int lane  = threadIdx.x & 31;
    int rowid = blockIdx.x * 8 + warp;            // b*NSEQ + n
    int n     = rowid & (NSEQ - 1);
    const float4* row = (const float4*)(sim + (size_t)rowid * NSEQ);

    float tv[MAXK];
    int   ti[MAXK];
#pragma unroll
    for (int i = 0; i < MAXK; i++) { tv[i] = -3.0e38f; ti[i] = 0x7fffffff; }

    // each lane loads 16 float4 (64 values), maintains sorted top-12
#pragma unroll
    for (int c = 0; c < 16; c++) {
        float4 v4 = row[c * 32 + lane];
        int base = (c * 32 + lane) * 4;
        float vv[4] = {v4.x, v4.y, v4.z, v4.w};
#pragma unroll
        for (int e = 0; e < 4; e++) {
            float v = vv[e]; int idx = base + e;
            if (pr_better(v, idx, tv[MAXK - 1], ti[MAXK - 1])) {
                tv[MAXK - 1] = v; ti[MAXK - 1] = idx;
#pragma unroll
                for (int s = MAXK - 1; s > 0; s--) {
                    if (pr_better(tv[s], ti[s], tv[s - 1], ti[s - 1])) {
                        float t0 = tv[s]; tv[s] = tv[s - 1]; tv[s - 1] = t0;
                        int  i0 = ti[s]; ti[s] = ti[s - 1]; ti[s - 1] = i0;
                    }
                }
            }
        }
    }

    int kp1 = *kptr + 1;
    if (kp1 > MAXK) kp1 = MAXK;
    for (int it = 0; it < kp1; it++) {
        float cand = tv[0]; int cidx = ti[0];
#pragma unroll
        for (int off = 16; off; off >>= 1) {
            float ov = __shfl_xor_sync(0xffffffffu, cand, off);
            int   oi = __shfl_xor_sync(0xffffffffu, cidx, off);
            if (pr_better(ov, oi, cand, cidx)) { cand = ov; cidx = oi; }
        }
        // winner lane pops its head (indices are globally unique -> exactly one lane)
        if (ti[0] == cidx) {
#pragma unroll
            for (int s = 0; s < MAXK - 1; s++) { tv[s] = tv[s + 1]; ti[s] = ti[s + 1]; }
            tv[MAXK - 1] = -3.0e38f; ti[MAXK - 1] = 0x7fffffff;
        }
        if (lane == 0) {
            atomicOr(&g_adj[(size_t)rowid * MW + (cidx >> 5)], 1u << (cidx & 31));
            atomicOr(&g_adj[(size_t)(rowid - n + cidx) * MW + (n >> 5)], 1u << (n & 31));
        }
    }
}

// ---------------- 5) sparse masked attention: one warp per (row, head) ----------------
__global__ __launch_bounds__(128) void attn_kernel(const float* __restrict__ q,
                                                   const float* __restrict__ k,
                                                   const float* __restrict__ v,
                                                   float* __restrict__ out) {
    int rowid = blockIdx.x;          // b*NSEQ + n
    int h    = threadIdx.x >> 5;
    int lane = threadIdx.x & 31;
    __shared__ unsigned mask[MW];
    if (threadIdx.x < MW) mask[threadIdx.x] = g_adj[(size_t)rowid * MW + threadIdx.x];
    __syncthreads();

    size_t qbase = (size_t)rowid * DM + h * DH;
    float2 qv = *(const float2*)(q + qbase + 2 * lane);
    int b = rowid >> 11;             // / NSEQ
    size_t kvbase = (size_t)b * NSEQ * DM + h * DH + 2 * lane;

    float mmax = -3.0e38f, den = 0.0f, a0 = 0.0f, a1 = 0.0f;
    for (int w = 0; w < MW; w++) {
        unsigned mwd = mask[w];
        while (mwd) {
            int bit = __ffs(mwd) - 1;
            mwd &= mwd - 1;
            int m = w * 32 + bit;
            size_t off = kvbase + (size_t)m * DM;
            float2 kv = *(const float2*)(k + off);
            float s = qv.x * kv.x + qv.y * kv.y;
#pragma unroll
            for (int o2 = 16; o2; o2 >>= 1) s += __shfl_xor_sync(0xffffffffu, s, o2);
            s *= 0.125f;  // 1/sqrt(64)
            float2 vv = *(const float2*)(v + off);
            if (s > mmax) {
                float c = __expf(mmax - s);
                den *= c; a0 *= c; a1 *= c; mmax = s;
            }
            float e = __expf(s - mmax);
            den += e; a0 += e * vv.x; a1 += e * vv.y;
        }
    }
    float inv = 1.0f / den;
    *(float2*)(out + qbase + 2 * lane) = make_float2(a0 * inv, a1 * inv);
}

// ---------------- 6) output projection GEMM ----------------
__global__ __launch_bounds__(256) void wo_kernel(const float* __restrict__ A,
                                                 const float* __restrict__ Bm,
                                                 float* __restrict__ C) {
    __shared__ float As[16][132];
    __shared__ float Bs[16][132];
    int m0 = blockIdx.y * 128, n0 = blockIdx.x * 128;
    float acc[8][8];
    gemm_body<0>(A, Bm, m0, n0, DM, acc, As, Bs);
    int tid = threadIdx.x;
    int tx = tid & 15, ty = tid >> 4;
#pragma unroll
    for (int i = 0; i < 8; i++) {
        float* cr = C + (size_t)(m0 + ty * 8 + i) * DM + n0 + tx * 8;
        *(float4*)cr       = make_float4(acc[i][0], acc[i][1], acc[i][2], acc[i][3]);
        *(float4*)(cr + 4) = make_float4(acc[i][4], acc[i][5], acc[i][6], acc[i][7]);
    }
}

// ---------------- 7) residual + bias + LayerNorm (one warp per row) ----------------
__global__ __launch_bounds__(256) void ln_kernel(const float* __restrict__ x,
                                                 const float* __restrict__ o,
                                                 const float* __restrict__ bo,
                                                 const float* __restrict__ gamma,
                                                 const float* __restrict__ beta,
                                                 float* __restrict__ out) {
    int row  = blockIdx.x * 8 + (threadIdx.x >> 5);
    int lane = threadIdx.x & 31;
    size_t base = (size_t)row * DM;
    const float4* x4 = (const float4*)(x + base);
    const float4* o4 = (const float4*)(o + base);
    const float4* b4 = (const float4*)bo;
    float4 xa = x4[lane], xb = x4[lane + 32];
    float4 oa = o4[lane], ob = o4[lane + 32];
    float4 ba = b4[lane], bb = b4[lane + 32];
    float t[8];
    t[0] = xa.x + oa.x + ba.x; t[1] = xa.y + oa.y + ba.y;
    t[2] = xa.z + oa.z + ba.z; t[3] = xa.w + oa.w + ba.w;
    t[4] = xb.x + ob.x + bb.x; t[5] = xb.y + ob.y + bb.y;
    t[6] = xb.z + ob.z + bb.z; t[7] = xb.w + ob.w + bb.w;
    float sum = 0.0f;
#pragma unroll
    for (int i = 0; i < 8; i++) sum += t[i];
#pragma unroll
    for (int off = 16; off; off >>= 1) sum += __shfl_xor_sync(0xffffffffu, sum, off);
    float mu = sum * (1.0f / 256.0f);
    float vs = 0.0f;
#pragma unroll
    for (int i = 0; i < 8; i++) { float d = t[i] - mu; vs += d * d; }
#pragma unroll
    for (int off = 16; off; off >>= 1) vs += __shfl_xor_sync(0xffffffffu, vs, off);
    float r = rsqrtf(vs * (1.0f / 256.0f) + 1e-5f);
    const float4* g4 = (const float4*)gamma;
    const float4* be4 = (const float4*)beta;
    float4 ga = g4[lane], gb = g4[lane + 32];
    float4 ea = be4[lane], eb = be4[lane + 32];
    float4 y0 = make_float4((t[0]-mu)*r*ga.x + ea.x, (t[1]-mu)*r*ga.y + ea.y,
                            (t[2]-mu)*r*ga.z + ea.z, (t[3]-mu)*r*ga.w + ea.w);
    float4 y1 = make_float4((t[4]-mu)*r*gb.x + eb.x, (t[5]-mu)*r*gb.y + eb.y,
                            (t[6]-mu)*r*gb.z + eb.z, (t[7]-mu)*r*gb.w + eb.w);
    float4* op = (float4*)(out + base);
    op[lane] = y0;
    op[lane + 32] = y1;
}

// ---------------- host launcher ----------------
extern "C" void kernel_launch(void* const* d_in, const int* in_sizes, int n_in,
                              void* d_out, int out_size) {
    const float* x     = (const float*)d_in[0];
    const float* Wq    = (const float*)d_in[1];
    const float* Wk    = (const float*)d_in[2];
    const float* Wv    = (const float*)d_in[3];
    const float* Wo    = (const float*)d_in[4];
    const float* bo    = (const float*)d_in[5];
    const float* gamma = (const float*)d_in[6];
    const float* beta  = (const float*)d_in[7];
    const int*   kn    = (const int*)d_in[8];
    float* out = (float*)d_out;

    float *xn, *sim, *q, *k, *v, *att, *o;
    cudaGetSymbolAddress((void**)&xn,  g_xn);
    cudaGetSymbolAddress((void**)&sim, g_sim);
    cudaGetSymbolAddress((void**)&q,   g_q);
    cudaGetSymbolAddress((void**)&k,   g_k);
    cudaGetSymbolAddress((void**)&v,   g_v);
    cudaGetSymbolAddress((void**)&att, g_att);
    cudaGetSymbolAddress((void**)&o,   g_o);

    // 1) normalize rows
    normalize_kernel<<<ROWS / 8, 256>>>(x, xn);

    // 2) batched symmetric similarity: upper-triangular tiles only (136 of 256)
    dim3 gsim(136, 1, BB);
    symgemm_kernel<<<gsim, 256>>>(xn, sim);

    // 3) adjacency bitmask
    zero_adj_kernel<<<(ROWS * MW) / 256, 256>>>();
    topk_kernel<<<ROWS / 8, 256>>>(sim, kn);

    // 4) QKV projections in one launch (z selects weight/output)
    dim3 gp(DM / 128, ROWS / 128, 3);
    proj_kernel<<<gp, 256>>>(x, Wq, Wk, Wv, q, k, v);

    // 5) sparse masked attention
    attn_kernel<<<ROWS, 128>>>(q, k, v, att);

    // 6) output projection + residual + bias + LayerNorm
    dim3 gw(DM / 128, ROWS / 128, 1);
    wo_kernel<<<gw, 256>>>(att, Wo, o);
    ln_kernel<<<ROWS / 8, 256>>>(x, o, bo, gamma, beta, out);
}

// round 3
// speedup vs baseline: 1.2940x; 1.1204x over previous
#include <cuda_runtime.h>
#include <math.h>

#define BB 4
#define NSEQ 2048
#define DM 256
#define NH 4
#define DH 64
#define MW (NSEQ / 32)   // 64 mask words per row
#define ROWS (BB * NSEQ) // 8192

// ---------------- scratch (static device globals; no allocation) ----------------
__device__ float    g_xn [ROWS * DM];
__device__ float    g_sim[(size_t)BB * NSEQ * NSEQ];   // 64 MB
__device__ unsigned g_adj[ROWS * MW];                  // 2 MB bitmask
__device__ float    g_q  [ROWS * DM];
__device__ float    g_k  [ROWS * DM];
__device__ float    g_v  [ROWS * DM];
__device__ float    g_att[ROWS * DM];
__device__ float    g_o  [ROWS * DM];

// ---------------- 1) row L2-normalize ----------------
__global__ __launch_bounds__(256) void normalize_kernel(const float* __restrict__ x,
                                                        float* __restrict__ xn) {
    int row  = blockIdx.x * 8 + (threadIdx.x >> 5);
    int lane = threadIdx.x & 31;
    const float4* xr = (const float4*)(x + (size_t)row * DM);
    float4 a = xr[lane];
    float4 b = xr[lane + 32];
    float s = a.x*a.x + a.y*a.y + a.z*a.z + a.w*a.w
            + b.x*b.x + b.y*b.y + b.z*b.z + b.w*b.w;
#pragma unroll
    for (int off = 16; off; off >>= 1) s += __shfl_xor_sync(0xffffffffu, s, off);
    float inv = 1.0f / fmaxf(sqrtf(s), 1e-12f);
    float4* o = (float4*)(xn + (size_t)row * DM);
    o[lane]      = make_float4(a.x*inv, a.y*inv, a.z*inv, a.w*inv);
    o[lane + 32] = make_float4(b.x*inv, b.y*inv, b.z*inv, b.w*inv);
}

// ---------------- generic fp32 GEMM body: 128x128 tile, 8x8 microtile, 256 thr ----------------
template <int TRANSB>
__device__ __forceinline__ void gemm_body(const float* __restrict__ A,
                                          const float* __restrict__ Bm,
                                          int m0, int n0, int Nn,
                                          float acc[8][8],
                                          float As[16][132], float Bs[16][132]) {
    int tid = threadIdx.x;
    int tx = tid & 15, ty = tid >> 4;
#pragma unroll
    for (int i = 0; i < 8; i++)
#pragma unroll
        for (int j = 0; j < 8; j++) acc[i][j] = 0.0f;

    for (int k0 = 0; k0 < DM; k0 += 16) {
#pragma unroll
        for (int t = 0; t < 2; t++) {
            int idx = tid + t * 256;          // 0..511 float4 slots
            int row = idx >> 2, qq = idx & 3;
            float4 v4 = *(const float4*)(A + (size_t)(m0 + row) * DM + k0 + qq * 4);
            As[qq*4+0][row] = v4.x; As[qq*4+1][row] = v4.y;
            As[qq*4+2][row] = v4.z; As[qq*4+3][row] = v4.w;
        }
        if (TRANSB) {
#pragma unroll
            for (int t = 0; t < 2; t++) {
                int idx = tid + t * 256;
                int row = idx >> 2, qq = idx & 3;
                float4 v4 = *(const float4*)(Bm + (size_t)(n0 + row) * DM + k0 + qq * 4);
                Bs[qq*4+0][row] = v4.x; Bs[qq*4+1][row] = v4.y;
                Bs[qq*4+2][row] = v4.z; Bs[qq*4+3][row] = v4.w;
            }
        } else {
#pragma unroll
            for (int t = 0; t < 2; t++) {
                int idx = tid + t * 256;
                int kk = idx >> 5, nq = idx & 31;
                *(float4*)&Bs[kk][nq * 4] =
                    *(const float4*)(Bm + (size_t)(k0 + kk) * Nn + n0 + nq * 4);
            }
        }
        __syncthreads();
#pragma unroll
        for (int kk = 0; kk < 16; kk++) {
            float a[8], bv[8];
            *(float4*)(a)      = *(const float4*)&As[kk][ty * 8];
            *(float4*)(a + 4)  = *(const float4*)&As[kk][ty * 8 + 4];
            *(float4*)(bv)     = *(const float4*)&Bs[kk][tx * 8];
            *(float4*)(bv + 4) = *(const float4*)&Bs[kk][tx * 8 + 4];
#pragma unroll
            for (int i = 0; i < 8; i++)
#pragma unroll
                for (int j = 0; j < 8; j++) acc[i][j] = fmaf(a[i], bv[j], acc[i][j]);
        }
        __syncthreads();
    }
}

// ---------------- 2) symmetric similarity GEMM: only upper-triangular tiles ----------------
__global__ __launch_bounds__(256) void symgemm_kernel(const float* __restrict__ xn,
                                                      float* __restrict__ C) {
    __shared__ float As[16][132];
    __shared__ float Bs[16][132];
    const float* A = xn + (size_t)blockIdx.z * NSEQ * DM;
    float* Cb = C + (size_t)blockIdx.z * NSEQ * NSEQ;

    int t = blockIdx.x, ti = 0;
    while (t >= 16 - ti) { t -= 16 - ti; ti++; }
    int tj = ti + t;
    int m0 = ti * 128, n0 = tj * 128;

    float acc[8][8];
    gemm_body<1>(A, A, m0, n0, NSEQ, acc, As, Bs);

    int tid = threadIdx.x;
    int tx = tid & 15, ty = tid >> 4;
#pragma unroll
    for (int i = 0; i < 8; i++) {
        float* cr = Cb + (size_t)(m0 + ty * 8 + i) * NSEQ + n0 + tx * 8;
        *(float4*)cr       = make_float4(acc[i][0], acc[i][1], acc[i][2], acc[i][3]);
        *(float4*)(cr + 4) = make_float4(acc[i][4], acc[i][5], acc[i][6], acc[i][7]);
    }
    if (ti != tj) {
#pragma unroll
        for (int j = 0; j < 8; j++) {
            float* cr = Cb + (size_t)(n0 + tx * 8 + j) * NSEQ + m0 + ty * 8;
            *(float4*)cr       = make_float4(acc[0][j], acc[1][j], acc[2][j], acc[3][j]);
            *(float4*)(cr + 4) = make_float4(acc[4][j], acc[5][j], acc[6][j], acc[7][j]);
        }
    }
}

// ---------------- standard GEMM (projections) with blockIdx.z B/C select ----------------
__global__ __launch_bounds__(256) void proj_kernel(const float* __restrict__ A,
                                                   const float* __restrict__ B0,
                                                   const float* __restrict__ B1,
                                                   const float* __restrict__ B2,
                                                   float* __restrict__ C0,
                                                   float* __restrict__ C1,
                                                   float* __restrict__ C2) {
    __shared__ float As[16][132];
    __shared__ float Bs[16][132];
    int z = blockIdx.z;
    const float* Bm = (z == 0) ? B0 : ((z == 1) ? B1 : B2);
    float*       C  = (z == 0) ? C0 : ((z == 1) ? C1 : C2);
    int m0 = blockIdx.y * 128, n0 = blockIdx.x * 128;
    float acc[8][8];
    gemm_body<0>(A, Bm, m0, n0, DM, acc, As, Bs);
    int tid = threadIdx.x;
    int tx = tid & 15, ty = tid >> 4;
#pragma unroll
    for (int i = 0; i < 8; i++) {
        float* cr = C + (size_t)(m0 + ty * 8 + i) * DM + n0 + tx * 8;
        *(float4*)cr       = make_float4(acc[i][0], acc[i][1], acc[i][2], acc[i][3]);
        *(float4*)(cr + 4) = make_float4(acc[i][4], acc[i][5], acc[i][6], acc[i][7]);
    }
}

// ---------------- 3) adjacency ----------------
__global__ void zero_adj_kernel() {
    g_adj[blockIdx.x * blockDim.x + threadIdx.x] = 0u;
}

__device__ __forceinline__ bool pr_better(float v, int i, float v2, int i2) {
    return v > v2 || (v == v2 && i < i2);
}

// block-per-row top-(k+1): 8 vals/thread in regs; per pop: 8-cmp local scan,
// 5-shuffle warp argmax, 3-shuffle cross-warp step in warp 0, broadcast.
// Ties -> smaller index (matches jax.lax.top_k).
__global__ __launch_bounds__(256) void topk_kernel(const float* __restrict__ sim,
                                                   const int* __restrict__ kptr) {
    int rowid = blockIdx.x;          // b*NSEQ + n
    int n     = rowid & (NSEQ - 1);
    int tid   = threadIdx.x;
    int lane  = tid & 31;
    int warp  = tid >> 5;
    const float4* row4 = (const float4*)(sim + (size_t)rowid * NSEQ);

    // thread tid owns columns 4*tid..4*tid+3 and 1024+4*tid..1024+4*tid+3
    float4 r0 = row4[tid];
    float4 r1 = row4[tid + 256];
    float v[8] = {r0.x, r0.y, r0.z, r0.w, r1.x, r1.y, r1.z, r1.w};

    __shared__ float sv[8];
    __shared__ int   si[8];
    __shared__ int   swin;

    int kp1 = *kptr + 1;
    for (int it = 0; it < kp1; it++) {
        // local argmax over 8 register values (statically indexed, no divergence)
        float bv = -3.0e38f; int bi = 0x7fffffff;
#pragma unroll
        for (int i = 0; i < 8; i++) {
            int idx = 4 * tid + (i < 4 ? i : 1020 + i);   // i>=4 -> 1024 + 4*tid + (i-4)
            if (pr_better(v[i], idx, bv, bi)) { bv = v[i]; bi = idx; }
        }
        // warp argmax
#pragma unroll
        for (int off = 16; off; off >>= 1) {
            float ov = __shfl_xor_sync(0xffffffffu, bv, off);
            int   oi = __shfl_xor_sync(0xffffffffu, bi, off);
            if (pr_better(ov, oi, bv, bi)) { bv = ov; bi = oi; }
        }
        if (lane == 0) { sv[warp] = bv; si[warp] = bi; }
        __syncthreads();
        // cross-warp argmax over 8 leaders (warp 0, lanes 0-7)
        if (warp == 0) {
            float wv = (lane < 8) ? sv[lane] : -3.0e38f;
            int   wi = (lane < 8) ? si[lane] : 0x7fffffff;
#pragma unroll
            for (int off = 4; off; off >>= 1) {
                float ov = __shfl_xor_sync(0xffffffffu, wv, off);
                int   oi = __shfl_xor_sync(0xffffffffu, wi, off);
                if (pr_better(ov, oi, wv, wi)) { wv = ov; wi = oi; }
            }
            if (lane == 0) {
                swin = wi;
                atomicOr(&g_adj[(size_t)rowid * MW + (wi >> 5)], 1u << (wi & 31));
                atomicOr(&g_adj[(size_t)(rowid - n + wi) * MW + (n >> 5)], 1u << (n & 31));
            }
        }
        __syncthreads();
        int widx = swin;
        // pop: the owning thread kills its slot (predicated selects, static indexing)
        if (((widx & 1023) >> 2) == tid) {
            int slot = (widx & 3) + ((widx >> 10) << 2);
#pragma unroll
            for (int s = 0; s < 8; s++) if (s == slot) v[s] = -3.0e38f;
        }
        __syncthreads();   // protect sv/si/swin from next-iteration overwrite
    }
}

// ---------------- 5) sparse masked attention: one warp per (row, head) ----------------
__global__ __launch_bounds__(128) void attn_kernel(const float* __restrict__ q,
                                                   const float* __restrict__ k,
                                                   const float* __restrict__ v,
                                                   float* __restrict__ out) {
    int rowid = blockIdx.x;          // b*NSEQ + n
    int h    = threadIdx.x >> 5;
    int lane = threadIdx.x & 31;
    __shared__ unsigned mask[MW];
    if (threadIdx.x < MW) mask[threadIdx.x] = g_adj[(size_t)rowid * MW + threadIdx.x];
    __syncthreads();

    size_t qbase = (size_t)rowid * DM + h * DH;
    float2 qv = *(const float2*)(q + qbase + 2 * lane);
    int b = rowid >> 11;             // / NSEQ
    size_t kvbase = (size_t)b * NSEQ * DM + h * DH + 2 * lane;

    float mmax = -3.0e38f, den = 0.0f, a0 = 0.0f, a1 = 0.0f;
    for (int w = 0; w < MW; w++) {
        unsigned mwd = mask[w];
        while (mwd) {
            int bit = __ffs(mwd) - 1;
            mwd &= mwd - 1;
            int m = w * 32 + bit;
            size_t off = kvbase + (size_t)m * DM;
            float2 kv = *(const float2*)(k + off);
            float s = qv.x * kv.x + qv.y * kv.y;
#pragma unroll
            for (int o2 = 16; o2; o2 >>= 1) s += __shfl_xor_sync(0xffffffffu, s, o2);
            s *= 0.125f;  // 1/sqrt(64)
            float2 vv = *(const float2*)(v + off);
            if (s > mmax) {
                float c = __expf(mmax - s);
                den *= c; a0 *= c; a1 *= c; mmax = s;
            }
            float e = __expf(s - mmax);
            den += e; a0 += e * vv.x; a1 += e * vv.y;
        }
    }
    float inv = 1.0f / den;
    *(float2*)(out + qbase + 2 * lane) = make_float2(a0 * inv, a1 * inv);
}

// ---------------- 6) output projection GEMM ----------------
__global__ __launch_bounds__(256) void wo_kernel(const float* __restrict__ A,
                                                 const float* __restrict__ Bm,
                                                 float* __restrict__ C) {
    __shared__ float As[16][132];
    __shared__ float Bs[16][132];
    int m0 = blockIdx.y * 128, n0 = blockIdx.x * 128;
    float acc[8][8];
    gemm_body<0>(A, Bm, m0, n0, DM, acc, As, Bs);
    int tid = threadIdx.x;
    int tx = tid & 15, ty = tid >> 4;
#pragma unroll
    for (int i = 0; i < 8; i++) {
        float* cr = C + (size_t)(m0 + ty * 8 + i) * DM + n0 + tx * 8;
        *(float4*)cr       = make_float4(acc[i][0], acc[i][1], acc[i][2], acc[i][3]);
        *(float4*)(cr + 4) = make_float4(acc[i][4], acc[i][5], acc[i][6], acc[i][7]);
    }
}

// ---------------- 7) residual + bias + LayerNorm (one warp per row) ----------------
__global__ __launch_bounds__(256) void ln_kernel(const float* __restrict__ x,
                                                 const float* __restrict__ o,
                                                 const float* __restrict__ bo,
                                                 const float* __restrict__ gamma,
                                                 const float* __restrict__ beta,
                                                 float* __restrict__ out) {
    int row  = blockIdx.x * 8 + (threadIdx.x >> 5);
    int lane = threadIdx.x & 31;
    size_t base = (size_t)row * DM;
    const float4* x4 = (const float4*)(x + base);
    const float4* o4 = (const float4*)(o + base);
    const float4* b4 = (const float4*)bo;
    float4 xa = x4[lane], xb = x4[lane + 32];
    float4 oa = o4[lane], ob = o4[lane + 32];
    float4 ba = b4[lane], bb = b4[lane + 32];
    float t[8];
    t[0] = xa.x + oa.x + ba.x; t[1] = xa.y + oa.y + ba.y;
    t[2] = xa.z + oa.z + ba.z; t[3] = xa.w + oa.w + ba.w;
    t[4] = xb.x + ob.x + bb.x; t[5] = xb.y + ob.y + bb.y;
    t[6] = xb.z + ob.z + bb.z; t[7] = xb.w + ob.w + bb.w;
    float sum = 0.0f;
#pragma unroll
    for (int i = 0; i < 8; i++) sum += t[i];
#pragma unroll
    for (int off = 16; off; off >>= 1) sum += __shfl_xor_sync(0xffffffffu, sum, off);
    float mu = sum * (1.0f / 256.0f);
    float vs = 0.0f;
#pragma unroll
    for (int i = 0; i < 8; i++) { float d = t[i] - mu; vs += d * d; }
#pragma unroll
    for (int off = 16; off; off >>= 1) vs += __shfl_xor_sync(0xffffffffu, vs, off);
    float r = rsqrtf(vs * (1.0f / 256.0f) + 1e-5f);
    const float4* g4 = (const float4*)gamma;
    const float4* be4 = (const float4*)beta;
    float4 ga = g4[lane], gb = g4[lane + 32];
    float4 ea = be4[lane], eb = be4[lane + 32];
    float4 y0 = make_float4((t[0]-mu)*r*ga.x + ea.x, (t[1]-mu)*r*ga.y + ea.y,
                            (t[2]-mu)*r*ga.z + ea.z, (t[3]-mu)*r*ga.w + ea.w);
    float4 y1 = make_float4((t[4]-mu)*r*gb.x + eb.x, (t[5]-mu)*r*gb.y + eb.y,
                            (t[6]-mu)*r*gb.z + eb.z, (t[7]-mu)*r*gb.w + eb.w);
    float4* op = (float4*)(out + base);
    op[lane] = y0;
    op[lane + 32] = y1;
}

// ---------------- host launcher ----------------
extern "C" void kernel_launch(void* const* d_in, const int* in_sizes, int n_in,
                              void* d_out, int out_size) {
    const float* x     = (const float*)d_in[0];
    const float* Wq    = (const float*)d_in[1];
    const float* Wk    = (const float*)d_in[2];
    const float* Wv    = (const float*)d_in[3];
    const float* Wo    = (const float*)d_in[4];
    const float* bo    = (const float*)d_in[5];
    const float* gamma = (const float*)d_in[6];
    const float* beta  = (const float*)d_in[7];
    const int*   kn    = (const int*)d_in[8];
    float* out = (float*)d_out;

    float *xn, *sim, *q, *k, *v, *att, *o;
    cudaGetSymbolAddress((void**)&xn,  g_xn);
    cudaGetSymbolAddress((void**)&sim, g_sim);
    cudaGetSymbolAddress((void**)&q,   g_q);
    cudaGetSymbolAddress((void**)&k,   g_k);
    cudaGetSymbolAddress((void**)&v,   g_v);
    cudaGetSymbolAddress((void**)&att, g_att);
    cudaGetSymbolAddress((void**)&o,   g_o);

    // 1) normalize rows
    normalize_kernel<<<ROWS / 8, 256>>>(x, xn);

    // 2) batched symmetric similarity: upper-triangular tiles only (136 of 256)
    dim3 gsim(136, 1, BB);
    symgemm_kernel<<<gsim, 256>>>(xn, sim);

    // 3) adjacency bitmask
    zero_adj_kernel<<<(ROWS * MW) / 256, 256>>>();
    topk_kernel<<<ROWS, 256>>>(sim, kn);

    // 4) QKV projections in one launch (z selects weight/output)
    dim3 gp(DM / 128, ROWS / 128, 3);
    proj_kernel<<<gp, 256>>>(x, Wq, Wk, Wv, q, k, v);

    // 5) sparse masked attention
    attn_kernel<<<ROWS, 128>>>(q, k, v, att);

    // 6) output projection + residual + bias + LayerNorm
    dim3 gw(DM / 128, ROWS / 128, 1);
    wo_kernel<<<gw, 256>>>(att, Wo, o);
    ln_kernel<<<ROWS / 8, 256>>>(x, o, bo, gamma, beta, out);
}

// round 4
// speedup vs baseline: 1.4639x; 1.1313x over previous
#include <cuda_runtime.h>
#include <math.h>

#define BB 4
#define NSEQ 2048
#define DM 256
#define NH 4
#define DH 64
#define MW (NSEQ / 32)   // 64 mask words per row
#define ROWS (BB * NSEQ) // 8192

// ---------------- scratch (static device globals; no allocation) ----------------
__device__ float    g_xn [ROWS * DM];
__device__ float    g_sim[(size_t)BB * NSEQ * NSEQ];   // 64 MB
__device__ unsigned g_adj[ROWS * MW];                  // 2 MB bitmask
__device__ float    g_q  [ROWS * DM];
__device__ float    g_k  [ROWS * DM];
__device__ float    g_v  [ROWS * DM];
__device__ float    g_att[ROWS * DM];
__device__ float    g_o  [ROWS * DM];

// ---------------- 1) row L2-normalize ----------------
__global__ __launch_bounds__(256) void normalize_kernel(const float* __restrict__ x,
                                                        float* __restrict__ xn) {
    int row  = blockIdx.x * 8 + (threadIdx.x >> 5);
    int lane = threadIdx.x & 31;
    const float4* xr = (const float4*)(x + (size_t)row * DM);
    float4 a = xr[lane];
    float4 b = xr[lane + 32];
    float s = a.x*a.x + a.y*a.y + a.z*a.z + a.w*a.w
            + b.x*b.x + b.y*b.y + b.z*b.z + b.w*b.w;
#pragma unroll
    for (int off = 16; off; off >>= 1) s += __shfl_xor_sync(0xffffffffu, s, off);
    float inv = 1.0f / fmaxf(sqrtf(s), 1e-12f);
    float4* o = (float4*)(xn + (size_t)row * DM);
    o[lane]      = make_float4(a.x*inv, a.y*inv, a.z*inv, a.w*inv);
    o[lane + 32] = make_float4(b.x*inv, b.y*inv, b.z*inv, b.w*inv);
}

// ---------------- double-buffered fp32 GEMM body: 128x128 tile, 8x8 microtile ----------------
// TRANSB=1: C[m][n] = sum_k A[m][k]*B[n][k]   (B row-major, ldb=256)
// TRANSB=0: C[m][n] = sum_k A[m][k]*B[k][n]   (B row-major, ldb=Nn)
template <int TRANSB>
__device__ __forceinline__ void gemm_body(const float* __restrict__ A,
                                          const float* __restrict__ Bm,
                                          int m0, int n0, int Nn,
                                          float acc[8][8],
                                          float As[2][16][132], float Bs[2][16][132]) {
    int tid = threadIdx.x;
    int tx = tid & 15, ty = tid >> 4;
    int arow = tid >> 2, aq = tid & 3;    // A/B-trans loader coords (rows arow, arow+64)
    int bkk = tid >> 5, nq = tid & 31;    // B-notrans loader coords (kk rows bkk, bkk+8)
#pragma unroll
    for (int i = 0; i < 8; i++)
#pragma unroll
        for (int j = 0; j < 8; j++) acc[i][j] = 0.0f;

    // prologue: chunk 0 into buffer 0
    {
        float4 a0 = *(const float4*)(A + (size_t)(m0 + arow) * DM + aq * 4);
        float4 a1 = *(const float4*)(A + (size_t)(m0 + arow + 64) * DM + aq * 4);
        As[0][aq*4+0][arow] = a0.x; As[0][aq*4+1][arow] = a0.y;
        As[0][aq*4+2][arow] = a0.z; As[0][aq*4+3][arow] = a0.w;
        As[0][aq*4+0][arow+64] = a1.x; As[0][aq*4+1][arow+64] = a1.y;
        As[0][aq*4+2][arow+64] = a1.z; As[0][aq*4+3][arow+64] = a1.w;
        if (TRANSB) {
            float4 b0 = *(const float4*)(Bm + (size_t)(n0 + arow) * DM + aq * 4);
            float4 b1 = *(const float4*)(Bm + (size_t)(n0 + arow + 64) * DM + aq * 4);
            Bs[0][aq*4+0][arow] = b0.x; Bs[0][aq*4+1][arow] = b0.y;
            Bs[0][aq*4+2][arow] = b0.z; Bs[0][aq*4+3][arow] = b0.w;
            Bs[0][aq*4+0][arow+64] = b1.x; Bs[0][aq*4+1][arow+64] = b1.y;
            Bs[0][aq*4+2][arow+64] = b1.z; Bs[0][aq*4+3][arow+64] = b1.w;
        } else {
            *(float4*)&Bs[0][bkk][nq * 4]     = *(const float4*)(Bm + (size_t)bkk * Nn + n0 + nq * 4);
            *(float4*)&Bs[0][bkk + 8][nq * 4] = *(const float4*)(Bm + (size_t)(bkk + 8) * Nn + n0 + nq * 4);
        }
    }
    __syncthreads();

    for (int kc = 0; kc < 16; kc++) {
        int cur = kc & 1, nxt = cur ^ 1;
        float4 pa0, pa1, pb0, pb1;
        if (kc < 15) {
            int k0 = (kc + 1) * 16;
            pa0 = *(const float4*)(A + (size_t)(m0 + arow) * DM + k0 + aq * 4);
            pa1 = *(const float4*)(A + (size_t)(m0 + arow + 64) * DM + k0 + aq * 4);
            if (TRANSB) {
                pb0 = *(const float4*)(Bm + (size_t)(n0 + arow) * DM + k0 + aq * 4);
                pb1 = *(const float4*)(Bm + (size_t)(n0 + arow + 64) * DM + k0 + aq * 4);
            } else {
                pb0 = *(const float4*)(Bm + (size_t)(k0 + bkk) * Nn + n0 + nq * 4);
                pb1 = *(const float4*)(Bm + (size_t)(k0 + bkk + 8) * Nn + n0 + nq * 4);
            }
        }
#pragma unroll
        for (int kk = 0; kk < 16; kk++) {
            float a[8], bv[8];
            *(float4*)(a)      = *(const float4*)&As[cur][kk][ty * 8];
            *(float4*)(a + 4)  = *(const float4*)&As[cur][kk][ty * 8 + 4];
            *(float4*)(bv)     = *(const float4*)&Bs[cur][kk][tx * 8];
            *(float4*)(bv + 4) = *(const float4*)&Bs[cur][kk][tx * 8 + 4];
#pragma unroll
            for (int i = 0; i < 8; i++)
#pragma unroll
                for (int j = 0; j < 8; j++) acc[i][j] = fmaf(a[i], bv[j], acc[i][j]);
        }
        if (kc < 15) {
            As[nxt][aq*4+0][arow] = pa0.x; As[nxt][aq*4+1][arow] = pa0.y;
            As[nxt][aq*4+2][arow] = pa0.z; As[nxt][aq*4+3][arow] = pa0.w;
            As[nxt][aq*4+0][arow+64] = pa1.x; As[nxt][aq*4+1][arow+64] = pa1.y;
            As[nxt][aq*4+2][arow+64] = pa1.z; As[nxt][aq*4+3][arow+64] = pa1.w;
            if (TRANSB) {
                Bs[nxt][aq*4+0][arow] = pb0.x; Bs[nxt][aq*4+1][arow] = pb0.y;
                Bs[nxt][aq*4+2][arow] = pb0.z; Bs[nxt][aq*4+3][arow] = pb0.w;
                Bs[nxt][aq*4+0][arow+64] = pb1.x; Bs[nxt][aq*4+1][arow+64] = pb1.y;
                Bs[nxt][aq*4+2][arow+64] = pb1.z; Bs[nxt][aq*4+3][arow+64] = pb1.w;
            } else {
                *(float4*)&Bs[nxt][bkk][nq * 4]     = pb0;
                *(float4*)&Bs[nxt][bkk + 8][nq * 4] = pb1;
            }
        }
        __syncthreads();
    }
}

// ---------------- 2) symmetric similarity GEMM: only upper-triangular tiles ----------------
__global__ __launch_bounds__(256) void symgemm_kernel(const float* __restrict__ xn,
                                                      float* __restrict__ C) {
    __shared__ float As[2][16][132];
    __shared__ float Bs[2][16][132];
    const float* A = xn + (size_t)blockIdx.z * NSEQ * DM;
    float* Cb = C + (size_t)blockIdx.z * NSEQ * NSEQ;

    int t = blockIdx.x, ti = 0;
    while (t >= 16 - ti) { t -= 16 - ti; ti++; }
    int tj = ti + t;
    int m0 = ti * 128, n0 = tj * 128;

    float acc[8][8];
    gemm_body<1>(A, A, m0, n0, NSEQ, acc, As, Bs);

    int tid = threadIdx.x;
    int tx = tid & 15, ty = tid >> 4;
#pragma unroll
    for (int i = 0; i < 8; i++) {
        float* cr = Cb + (size_t)(m0 + ty * 8 + i) * NSEQ + n0 + tx * 8;
        *(float4*)cr       = make_float4(acc[i][0], acc[i][1], acc[i][2], acc[i][3]);
        *(float4*)(cr + 4) = make_float4(acc[i][4], acc[i][5], acc[i][6], acc[i][7]);
    }
    if (ti != tj) {
#pragma unroll
        for (int j = 0; j < 8; j++) {
            float* cr = Cb + (size_t)(n0 + tx * 8 + j) * NSEQ + m0 + ty * 8;
            *(float4*)cr       = make_float4(acc[0][j], acc[1][j], acc[2][j], acc[3][j]);
            *(float4*)(cr + 4) = make_float4(acc[4][j], acc[5][j], acc[6][j], acc[7][j]);
        }
    }
}

// ---------------- QKV projections (z selects weight/output) ----------------
__global__ __launch_bounds__(256) void proj_kernel(const float* __restrict__ A,
                                                   const float* __restrict__ B0,
                                                   const float* __restrict__ B1,
                                                   const float* __restrict__ B2,
                                                   float* __restrict__ C0,
                                                   float* __restrict__ C1,
                                                   float* __restrict__ C2) {
    __shared__ float As[2][16][132];
    __shared__ float Bs[2][16][132];
    int z = blockIdx.z;
    const float* Bm = (z == 0) ? B0 : ((z == 1) ? B1 : B2);
    float*       C  = (z == 0) ? C0 : ((z == 1) ? C1 : C2);
    int m0 = blockIdx.y * 128, n0 = blockIdx.x * 128;
    float acc[8][8];
    gemm_body<0>(A, Bm, m0, n0, DM, acc, As, Bs);
    int tid = threadIdx.x;
    int tx = tid & 15, ty = tid >> 4;
#pragma unroll
    for (int i = 0; i < 8; i++) {
        float* cr = C + (size_t)(m0 + ty * 8 + i) * DM + n0 + tx * 8;
        *(float4*)cr       = make_float4(acc[i][0], acc[i][1], acc[i][2], acc[i][3]);
        *(float4*)(cr + 4) = make_float4(acc[i][4], acc[i][5], acc[i][6], acc[i][7]);
    }
}

// ---------------- 3) adjacency ----------------
__global__ void zero_adj_kernel() {
    g_adj[blockIdx.x * blockDim.x + threadIdx.x] = 0u;
}

__device__ __forceinline__ bool pr_better(float v, int i, float v2, int i2) {
    return v > v2 || (v == v2 && i < i2);
}

// block-per-row top-k. Self (diag, sim=1.0, guaranteed global max) handled directly;
// then k pops. Each thread presorts its 8 values (19-CE Batcher network) so every
// pop compares only heads: 5-shuffle warp argmax + 3-shuffle cross-warp + 2 barriers.
// Ties -> smaller index (matches jax.lax.top_k).
__global__ __launch_bounds__(256) void topk_kernel(const float* __restrict__ sim,
                                                   const int* __restrict__ kptr) {
    int rowid = blockIdx.x;          // b*NSEQ + n
    int n     = rowid & (NSEQ - 1);
    int tid   = threadIdx.x;
    int lane  = tid & 31;
    int warp  = tid >> 5;
    const float4* row4 = (const float4*)(sim + (size_t)rowid * NSEQ);

    float4 r0 = row4[tid];
    float4 r1 = row4[tid + 256];
    float v[8] = {r0.x, r0.y, r0.z, r0.w, r1.x, r1.y, r1.z, r1.w};
    int ti[8];
#pragma unroll
    for (int i = 0; i < 8; i++) ti[i] = (i < 4) ? (4 * tid + i) : (1024 + 4 * tid + i - 4);

    // self column: set its adjacency bit directly, remove from candidates
    if (((n & 1023) >> 2) == tid) {
        int slot = (n & 3) + ((n >> 10) << 2);
#pragma unroll
        for (int s = 0; s < 8; s++) if (s == slot) v[s] = -3.0e38f;
    }
    if (tid == 0)
        atomicOr(&g_adj[(size_t)rowid * MW + (n >> 5)], 1u << (n & 31));

    // presort descending (best at index 0): Batcher odd-even merge, 19 CEs
#define CE(a,b) { if (pr_better(v[b], ti[b], v[a], ti[a])) { \
        float tv_ = v[a]; v[a] = v[b]; v[b] = tv_; \
        int ii_ = ti[a]; ti[a] = ti[b]; ti[b] = ii_; } }
    CE(0,1) CE(2,3) CE(4,5) CE(6,7)
    CE(0,2) CE(1,3) CE(4,6) CE(5,7)
    CE(1,2) CE(5,6)
    CE(0,4) CE(1,5) CE(2,6) CE(3,7)
    CE(2,4) CE(3,5)
    CE(1,2) CE(3,4) CE(5,6)
#undef CE

    __shared__ float sv[8];
    __shared__ int   si[8];
    __shared__ int   swin;

    int kp = *kptr;   // self already handled; pop k more
    for (int it = 0; it < kp; it++) {
        float bv = v[0]; int bi = ti[0];
#pragma unroll
        for (int off = 16; off; off >>= 1) {
            float ov = __shfl_xor_sync(0xffffffffu, bv, off);
            int   oi = __shfl_xor_sync(0xffffffffu, bi, off);
            if (pr_better(ov, oi, bv, bi)) { bv = ov; bi = oi; }
        }
        if (lane == 0) { sv[warp] = bv; si[warp] = bi; }
        __syncthreads();
        if (warp == 0) {
            float wv = (lane < 8) ? sv[lane] : -3.0e38f;
            int   wi = (lane < 8) ? si[lane] : 0x7fffffff;
#pragma unroll
            for (int off = 4; off; off >>= 1) {
                float ov = __shfl_xor_sync(0xffffffffu, wv, off);
                int   oi = __shfl_xor_sync(0xffffffffu, wi, off);
                if (pr_better(ov, oi, wv, wi)) { wv = ov; wi = oi; }
            }
            if (lane == 0) {
                swin = wi;
                atomicOr(&g_adj[(size_t)rowid * MW + (wi >> 5)], 1u << (wi & 31));
                atomicOr(&g_adj[(size_t)(rowid - n + wi) * MW + (n >> 5)], 1u << (n & 31));
            }
        }
        __syncthreads();
        if (ti[0] == swin) {   // owning thread pops its head (sorted -> just shift)
#pragma unroll
            for (int s = 0; s < 7; s++) { v[s] = v[s + 1]; ti[s] = ti[s + 1]; }
            v[7] = -3.0e38f; ti[7] = 0x7fffffff;
        }
    }
}

// ---------------- 5) sparse masked attention: one warp per (row, head) ----------------
__global__ __launch_bounds__(128) void attn_kernel(const float* __restrict__ q,
                                                   const float* __restrict__ k,
                                                   const float* __restrict__ v,
                                                   float* __restrict__ out) {
    int rowid = blockIdx.x;          // b*NSEQ + n
    int h    = threadIdx.x >> 5;
    int lane = threadIdx.x & 31;
    __shared__ unsigned mask[MW];
    if (threadIdx.x < MW) mask[threadIdx.x] = g_adj[(size_t)rowid * MW + threadIdx.x];
    __syncthreads();

    size_t qbase = (size_t)rowid * DM + h * DH;
    float2 qv = *(const float2*)(q + qbase + 2 * lane);
    int b = rowid >> 11;             // / NSEQ
    size_t kvbase = (size_t)b * NSEQ * DM + h * DH + 2 * lane;

    float mmax = -3.0e38f, den = 0.0f, a0 = 0.0f, a1 = 0.0f;
    for (int w = 0; w < MW; w++) {
        unsigned mwd = mask[w];
        while (mwd) {
            int bit = __ffs(mwd) - 1;
            mwd &= mwd - 1;
            int m = w * 32 + bit;
            size_t off = kvbase + (size_t)m * DM;
            float2 kv = *(const float2*)(k + off);
            float s = qv.x * kv.x + qv.y * kv.y;
#pragma unroll
            for (int o2 = 16; o2; o2 >>= 1) s += __shfl_xor_sync(0xffffffffu, s, o2);
            s *= 0.125f;  // 1/sqrt(64)
            float2 vv = *(const float2*)(v + off);
            if (s > mmax) {
                float c = __expf(mmax - s);
                den *= c; a0 *= c; a1 *= c; mmax = s;
            }
            float e = __expf(s - mmax);
            den += e; a0 += e * vv.x; a1 += e * vv.y;
        }
    }
    float inv = 1.0f / den;
    *(float2*)(out + qbase + 2 * lane) = make_float2(a0 * inv, a1 * inv);
}

// ---------------- 6) output projection GEMM ----------------
__global__ __launch_bounds__(256) void wo_kernel(const float* __restrict__ A,
                                                 const float* __restrict__ Bm,
                                                 float* __restrict__ C) {
    __shared__ float As[2][16][132];
    __shared__ float Bs[2][16][132];
    int m0 = blockIdx.y * 128, n0 = blockIdx.x * 128;
    float acc[8][8];
    gemm_body<0>(A, Bm, m0, n0, DM, acc, As, Bs);
    int tid = threadIdx.x;
    int tx = tid & 15, ty = tid >> 4;
#pragma unroll
    for (int i = 0; i < 8; i++) {
        float* cr = C + (size_t)(m0 + ty * 8 + i) * DM + n0 + tx * 8;
        *(float4*)cr       = make_float4(acc[i][0], acc[i][1], acc[i][2], acc[i][3]);
        *(float4*)(cr + 4) = make_float4(acc[i][4], acc[i][5], acc[i][6], acc[i][7]);
    }
}

// ---------------- 7) residual + bias + LayerNorm (one warp per row) ----------------
__global__ __launch_bounds__(256) void ln_kernel(const float* __restrict__ x,
                                                 const float* __restrict__ o,
                                                 const float* __restrict__ bo,
                                                 const float* __restrict__ gamma,
                                                 const float* __restrict__ beta,
                                                 float* __restrict__ out) {
    int row  = blockIdx.x * 8 + (threadIdx.x >> 5);
    int lane = threadIdx.x & 31;
    size_t base = (size_t)row * DM;
    const float4* x4 = (const float4*)(x + base);
    const float4* o4 = (const float4*)(o + base);
    const float4* b4 = (const float4*)bo;
    float4 xa = x4[lane], xb = x4[lane + 32];
    float4 oa = o4[lane], ob = o4[lane + 32];
    float4 ba = b4[lane], bb = b4[lane + 32];
    float t[8];
    t[0] = xa.x + oa.x + ba.x; t[1] = xa.y + oa.y + ba.y;
    t[2] = xa.z + oa.z + ba.z; t[3] = xa.w + oa.w + ba.w;
    t[4] = xb.x + ob.x + bb.x; t[5] = xb.y + ob.y + bb.y;
    t[6] = xb.z + ob.z + bb.z; t[7] = xb.w + ob.w + bb.w;
    float sum = 0.0f;
#pragma unroll
    for (int i = 0; i < 8; i++) sum += t[i];
#pragma unroll
    for (int off = 16; off; off >>= 1) sum += __shfl_xor_sync(0xffffffffu, sum, off);
    float mu = sum * (1.0f / 256.0f);
    float vs = 0.0f;
#pragma unroll
    for (int i = 0; i < 8; i++) { float d = t[i] - mu; vs += d * d; }
#pragma unroll
    for (int off = 16; off; off >>= 1) vs += __shfl_xor_sync(0xffffffffu, vs, off);
    float r = rsqrtf(vs * (1.0f / 256.0f) + 1e-5f);
    const float4* g4 = (const float4*)gamma;
    const float4* be4 = (const float4*)beta;
    float4 ga = g4[lane], gb = g4[lane + 32];
    float4 ea = be4[lane], eb = be4[lane + 32];
    float4 y0 = make_float4((t[0]-mu)*r*ga.x + ea.x, (t[1]-mu)*r*ga.y + ea.y,
                            (t[2]-mu)*r*ga.z + ea.z, (t[3]-mu)*r*ga.w + ea.w);
    float4 y1 = make_float4((t[4]-mu)*r*gb.x + eb.x, (t[5]-mu)*r*gb.y + eb.y,
                            (t[6]-mu)*r*gb.z + eb.z, (t[7]-mu)*r*gb.w + eb.w);
    float4* op = (float4*)(out + base);
    op[lane] = y0;
    op[lane + 32] = y1;
}

// ---------------- host launcher ----------------
extern "C" void kernel_launch(void* const* d_in, const int* in_sizes, int n_in,
                              void* d_out, int out_size) {
    const float* x     = (const float*)d_in[0];
    const float* Wq    = (const float*)d_in[1];
    const float* Wk    = (const float*)d_in[2];
    const float* Wv    = (const float*)d_in[3];
    const float* Wo    = (const float*)d_in[4];
    const float* bo    = (const float*)d_in[5];
    const float* gamma = (const float*)d_in[6];
    const float* beta  = (const float*)d_in[7];
    const int*   kn    = (const int*)d_in[8];
    float* out = (float*)d_out;

    float *xn, *sim, *q, *k, *v, *att, *o;
    cudaGetSymbolAddress((void**)&xn,  g_xn);
    cudaGetSymbolAddress((void**)&sim, g_sim);
    cudaGetSymbolAddress((void**)&q,   g_q);
    cudaGetSymbolAddress((void**)&k,   g_k);
    cudaGetSymbolAddress((void**)&v,   g_v);
    cudaGetSymbolAddress((void**)&att, g_att);
    cudaGetSymbolAddress((void**)&o,   g_o);

    // one-time side-stream + events (created on first call, outside graph capture)
    static cudaStream_t s2 = nullptr;
    static cudaEvent_t evRoot = nullptr, evProj = nullptr;
    if (s2 == nullptr) {
        cudaStreamCreateWithFlags(&s2, cudaStreamNonBlocking);
        cudaEventCreateWithFlags(&evRoot, cudaEventDisableTiming);
        cudaEventCreateWithFlags(&evProj, cudaEventDisableTiming);
    }

    // fork: QKV projections depend only on x -> run concurrently with sim/topk chain
    cudaEventRecord(evRoot, 0);
    cudaStreamWaitEvent(s2, evRoot, 0);
    dim3 gp(DM / 128, ROWS / 128, 3);
    proj_kernel<<<gp, 256, 0, s2>>>(x, Wq, Wk, Wv, q, k, v);
    cudaEventRecord(evProj, s2);

    // main chain: normalize -> symgemm -> zero_adj -> topk
    normalize_kernel<<<ROWS / 8, 256>>>(x, xn);
    dim3 gsim(136, 1, BB);
    symgemm_kernel<<<gsim, 256>>>(xn, sim);
    zero_adj_kernel<<<(ROWS * MW) / 256, 256>>>();
    topk_kernel<<<ROWS, 256>>>(sim, kn);

    // join: attention needs q/k/v + adjacency
    cudaStreamWaitEvent(0, evProj, 0);
    attn_kernel<<<ROWS, 128>>>(q, k, v, att);

    // output projection + residual + bias + LayerNorm
    dim3 gw(DM / 128, ROWS / 128, 1);
    wo_kernel<<<gw, 256>>>(att, Wo, o);
    ln_kernel<<<ROWS / 8, 256>>>(x, o, bo, gamma, beta, out);
}